// round 5
// baseline (speedup 1.0000x reference)
#include <cuda_runtime.h>
#include <cstdint>

// out[dst[e], :] += w[e] * x[src[e], :]
// x: [N, 64] f32; edge_weight: [E] f32; edge_index: [2, E] int32; out: [N, 64] f32
//
// 16 lanes per edge-chunk (each LDG.128 covers 2 complete contiguous 256B rows
// warp-wide), 4 edges per thread for MLP=4 on the gather chains.
// Scatter via red.global.add.v4.f32 (one 16B L2 atomic per chunk).

static constexpr int F = 64;
static constexpr int THREADS = 256;

__global__ void __launch_bounds__(THREADS)
mp_scatter_kernel(const float* __restrict__ x,
                  const float* __restrict__ ew,
                  const int* __restrict__ ei,   // [2, E] int32
                  float* __restrict__ out,
                  int E)                        // main kernel covers E4 = E & ~3
{
    int idx = blockIdx.x * THREADS + threadIdx.x;   // one thread = chunk c of an edge quad
    int quads = E >> 2;
    int total = quads * 16;                          // 4M for E=1M
    if (idx >= total) return;

    int p = idx >> 4;           // edge quad id
    int c = idx & 15;           // chunk id within row
    int e0 = p * 4;             // 4-edge aligned -> int4/float4 loads

    // One vector load serves 4 edges; broadcast within the 16-lane group.
    int4   s4 = __ldcs(reinterpret_cast<const int4*>(ei + e0));
    int4   d4 = __ldcs(reinterpret_cast<const int4*>(ei + E + e0));
    float4 w4 = __ldcs(reinterpret_cast<const float4*>(ew + e0));

    long long co = (long long)(c * 4);

    // Four independent gather chains, front-batched (MLP=4).
    float4 va = __ldg(reinterpret_cast<const float4*>(x + (long long)s4.x * F + co));
    float4 vb = __ldg(reinterpret_cast<const float4*>(x + (long long)s4.y * F + co));
    float4 vc = __ldg(reinterpret_cast<const float4*>(x + (long long)s4.z * F + co));
    float4 vd = __ldg(reinterpret_cast<const float4*>(x + (long long)s4.w * F + co));

    va.x *= w4.x; va.y *= w4.x; va.z *= w4.x; va.w *= w4.x;
    vb.x *= w4.y; vb.y *= w4.y; vb.z *= w4.y; vb.w *= w4.y;
    vc.x *= w4.z; vc.y *= w4.z; vc.z *= w4.z; vc.w *= w4.z;
    vd.x *= w4.w; vd.y *= w4.w; vd.z *= w4.w; vd.w *= w4.w;

    float* pa = out + (long long)d4.x * F + co;
    float* pb = out + (long long)d4.y * F + co;
    float* pc = out + (long long)d4.z * F + co;
    float* pd = out + (long long)d4.w * F + co;
    asm volatile("red.global.add.v4.f32 [%0], {%1, %2, %3, %4};"
                 :: "l"(pa), "f"(va.x), "f"(va.y), "f"(va.z), "f"(va.w) : "memory");
    asm volatile("red.global.add.v4.f32 [%0], {%1, %2, %3, %4};"
                 :: "l"(pb), "f"(vb.x), "f"(vb.y), "f"(vb.z), "f"(vb.w) : "memory");
    asm volatile("red.global.add.v4.f32 [%0], {%1, %2, %3, %4};"
                 :: "l"(pc), "f"(vc.x), "f"(vc.y), "f"(vc.z), "f"(vc.w) : "memory");
    asm volatile("red.global.add.v4.f32 [%0], {%1, %2, %3, %4};"
                 :: "l"(pd), "f"(vd.x), "f"(vd.y), "f"(vd.z), "f"(vd.w) : "memory");
}

__global__ void __launch_bounds__(THREADS)
mp_scatter_tail(const float* __restrict__ x,
                const float* __restrict__ ew,
                const int* __restrict__ ei,
                float* __restrict__ out,
                int E, int e_start)
{
    int idx = blockIdx.x * THREADS + threadIdx.x;
    int n = (E - e_start) * 16;
    if (idx >= n) return;
    int e = e_start + (idx >> 4);
    int c = idx & 15;
    int   s = __ldg(&ei[e]);
    int   d = __ldg(&ei[E + e]);
    float w = __ldg(&ew[e]);
    float4 v = __ldg(reinterpret_cast<const float4*>(x + (long long)s * F + c * 4));
    v.x *= w; v.y *= w; v.z *= w; v.w *= w;
    float* dp = out + (long long)d * F + c * 4;
    asm volatile("red.global.add.v4.f32 [%0], {%1, %2, %3, %4};"
                 :: "l"(dp), "f"(v.x), "f"(v.y), "f"(v.z), "f"(v.w) : "memory");
}

extern "C" void kernel_launch(void* const* d_in, const int* in_sizes, int n_in,
                              void* d_out, int out_size)
{
    const float* x  = (const float*)d_in[0];
    const float* ew = (const float*)d_in[1];
    const int*   ei = (const int*)d_in[2];
    float* out = (float*)d_out;

    int E = in_sizes[2] / 2;

    cudaMemsetAsync(out, 0, (size_t)out_size * sizeof(float), 0);

    int quads = E >> 2;
    int total = quads * 16;
    int blocks = (total + THREADS - 1) / THREADS;
    mp_scatter_kernel<<<blocks, THREADS>>>(x, ew, ei, out, E);

    int e4 = quads * 4;
    if (e4 < E) {
        int n = (E - e4) * 16;
        mp_scatter_tail<<<(n + THREADS - 1) / THREADS, THREADS>>>(x, ew, ei, out, E, e4);
    }
}